// round 16
// baseline (speedup 1.0000x reference)
#include <cuda_runtime.h>
#include <cuda_fp16.h>
#include <cstdint>

// ---------------- problem constants ----------------
#define B_ROWS   8192
#define DFEAT    128
#define DKEEP    64
#define TILE     128
#define NSM      148
#define NUNITS   1024            // 2 matrices x 64 row tiles x 8 column chunks
#define NTHREADS 256

#define LOG2E 1.4426950408889634f
#define LN2   0.6931471805599453f
#define SHIFTB 32.0f

// smem byte offsets (dynamic smem)
#define SB_X     0
#define SB_Y0    16384
#define SB_Y1    32768
#define SB_RSUM0 49152            // float[128]
#define SB_RSUM1 (49152+512)
#define SMEM_BYTES (49152+1024)

// ---------------- scratch ----------------
__device__ __half g_ao [B_ROWS * DKEEP];  // a[:, ai]
__device__ __half g_iao[B_ROWS * DKEEP];  // v[:, ai]
__device__ __half g_io [B_ROWS * DKEEP];  // v[:, ii]
__device__ __half g_aio[B_ROWS * DKEEP];  // a[:, ii]
__device__ float  g_rsum[2 * B_ROWS];     // exp row sums (both matrices)
__device__ float  g_diag[2 * B_ROWS];     // diagonals

// ---------------- helpers ----------------
__device__ __forceinline__ uint32_t smem_u32(const void* p) {
    uint32_t a;
    asm("{ .reg .u64 t; cvta.to.shared.u64 t, %1; cvt.u32.u64 %0, t; }" : "=r"(a) : "l"(p));
    return a;
}

__device__ __forceinline__ void cp16(uint32_t dst, const void* src) {
    asm volatile("cp.async.cg.shared.global [%0], [%1], 16;" :: "r"(dst), "l"(src));
}
#define CP_COMMIT() asm volatile("cp.async.commit_group;" ::: "memory")
#define CP_WAIT(n)  asm volatile("cp.async.wait_group %0;" :: "n"(n) : "memory")

__device__ __forceinline__ void ldsm4(uint32_t r[4], uint32_t a) {
    asm volatile("ldmatrix.sync.aligned.m8n8.x4.shared.b16 {%0,%1,%2,%3}, [%4];"
        : "=r"(r[0]), "=r"(r[1]), "=r"(r[2]), "=r"(r[3]) : "r"(a));
}

// f32-accumulate MMA, D += A*B
__device__ __forceinline__ void mma16816_f(float c[4], const uint32_t a[4],
                                           uint32_t b0, uint32_t b1) {
    asm volatile(
        "mma.sync.aligned.m16n8k16.row.col.f32.f16.f16.f32 "
        "{%0,%1,%2,%3}, {%4,%5,%6,%7}, {%8,%9}, {%0,%1,%2,%3};"
        : "+f"(c[0]), "+f"(c[1]), "+f"(c[2]), "+f"(c[3])
        : "r"(a[0]), "r"(a[1]), "r"(a[2]), "r"(a[3]), "r"(b0), "r"(b1));
}

__device__ __forceinline__ float ex2f(float t) {
    float e;
    asm("ex2.approx.ftz.f32 %0, %1;" : "=f"(e) : "f"(t));
    return e;
}

// exp-accumulate one f32 c-fragment (ungated -- R15 showed gates become branches)
__device__ __forceinline__ void exp_frag(const float (&v)[4], float& p0, float& p1,
                                         float& p2, float& p3) {
    p0 += ex2f(fmaf(v[0], LOG2E, -SHIFTB));
    p1 += ex2f(fmaf(v[1], LOG2E, -SHIFTB));
    p2 += ex2f(fmaf(v[2], LOG2E, -SHIFTB));
    p3 += ex2f(fmaf(v[3], LOG2E, -SHIFTB));
}

// compute tile into cur (32 rows x 64 cols per warp; 2 row-blocks share B frags);
// exp-process prev interleaved; B frags double-buffered across k-steps.
__device__ __forceinline__ void do_tile(
    uint32_t sbY,
    const uint32_t (&A)[2][4][4],
    const uint32_t (&browoff)[4], const uint32_t (&bxr)[4], int bko,
    float (&cur)[2][8][4], float (&prev)[2][8][4],
    float (&ps)[8])
{
#pragma unroll
    for (int rb = 0; rb < 2; rb++)
#pragma unroll
        for (int f = 0; f < 8; f++)
#pragma unroll
            for (int c = 0; c < 4; c++) cur[rb][f][c] = 0.f;

    uint32_t Bf[2][4][4];
#pragma unroll
    for (int nn = 0; nn < 4; nn++)
        ldsm4(Bf[0][nn], sbY + browoff[nn] + (((uint32_t)bko ^ bxr[nn]) << 4));
#pragma unroll
    for (int kk = 0; kk < 4; kk++) {
        const int cb = kk & 1, nb = cb ^ 1;
        mma16816_f(cur[0][0], A[0][kk], Bf[cb][0][0], Bf[cb][0][1]);
        mma16816_f(cur[0][1], A[0][kk], Bf[cb][0][2], Bf[cb][0][3]);
        if (kk < 3) {
#pragma unroll
            for (int nn = 0; nn < 4; nn++) {
                uint32_t addr = sbY + browoff[nn]
                              + (((uint32_t)(((kk + 1) << 1) + bko) ^ bxr[nn]) << 4);
                ldsm4(Bf[nb][nn], addr);
            }
        }
        exp_frag(prev[0][2 * kk], ps[0], ps[1], ps[2], ps[3]);
        mma16816_f(cur[0][2], A[0][kk], Bf[cb][1][0], Bf[cb][1][1]);
        mma16816_f(cur[0][3], A[0][kk], Bf[cb][1][2], Bf[cb][1][3]);
        exp_frag(prev[0][2 * kk + 1], ps[0], ps[1], ps[2], ps[3]);
        mma16816_f(cur[0][4], A[0][kk], Bf[cb][2][0], Bf[cb][2][1]);
        mma16816_f(cur[0][5], A[0][kk], Bf[cb][2][2], Bf[cb][2][3]);
        exp_frag(prev[1][2 * kk], ps[4], ps[5], ps[6], ps[7]);
        mma16816_f(cur[0][6], A[0][kk], Bf[cb][3][0], Bf[cb][3][1]);
        mma16816_f(cur[0][7], A[0][kk], Bf[cb][3][2], Bf[cb][3][3]);
        exp_frag(prev[1][2 * kk + 1], ps[4], ps[5], ps[6], ps[7]);
        mma16816_f(cur[1][0], A[1][kk], Bf[cb][0][0], Bf[cb][0][1]);
        mma16816_f(cur[1][1], A[1][kk], Bf[cb][0][2], Bf[cb][0][3]);
        mma16816_f(cur[1][2], A[1][kk], Bf[cb][1][0], Bf[cb][1][1]);
        mma16816_f(cur[1][3], A[1][kk], Bf[cb][1][2], Bf[cb][1][3]);
        mma16816_f(cur[1][4], A[1][kk], Bf[cb][2][0], Bf[cb][2][1]);
        mma16816_f(cur[1][5], A[1][kk], Bf[cb][2][2], Bf[cb][2][3]);
        mma16816_f(cur[1][6], A[1][kk], Bf[cb][3][0], Bf[cb][3][1]);
        mma16816_f(cur[1][7], A[1][kk], Bf[cb][3][2], Bf[cb][3][3]);
    }
}

// ---------------- gather (smem-staged, coalesced) ----------------
// Index buffers may be int32 or int64 (sniff; see earlier rounds). Each block
// stages 32 rows of a and v via fully coalesced loads, then gathers from smem.
__global__ void gather_kernel(const float* __restrict__ a, const float* __restrict__ v,
                              const int* __restrict__ ai32,
                              const int* __restrict__ ii32,
                              float* __restrict__ out, int out_size) {
    __shared__ float sa[32 * DFEAT], sv[32 * DFEAT];
    __shared__ int sai[DKEEP], sii[DKEEP];
    __shared__ int is64;
    const int tid = threadIdx.x;
    const int bid = blockIdx.x;
    if (bid == 0 && tid < out_size) out[tid] = 0.0f;
    if (bid < 64) g_rsum[bid * 256 + tid] = 0.0f;
    if (tid == 0) {
        int orr = 0;
#pragma unroll
        for (int k = 0; k < 32; k++) orr |= ai32[2 * k + 1] | ii32[2 * k + 1];
        is64 = (orr == 0) ? 1 : 0;
    }
    __syncthreads();
    if (tid < DKEEP) {
        int step = is64 ? 2 : 1;
        sai[tid] = ai32[tid * step] & (DFEAT - 1);
        sii[tid] = ii32[tid * step] & (DFEAT - 1);
    }
    // coalesced row staging: 32 rows x 128 cols = 4096 floats each
    const size_t base = (size_t)bid * 32 * DFEAT;
#pragma unroll
    for (int k = 0; k < 16; k++) {
        int i = tid + k * 256;
        sa[i] = a[base + i];
        sv[i] = v[base + i];
    }
    __syncthreads();
    // gather: 32 rows x 64 kept cols = 2048 elements, 8 per thread, coalesced writes
#pragma unroll
    for (int k = 0; k < 8; k++) {
        int i = tid + k * 256;
        int r = i >> 6, kk = i & 63;
        int ia = sai[kk], iv = sii[kk];
        size_t o = (size_t)bid * 32 * DKEEP + i;
        g_ao [o] = __float2half(sa[r * DFEAT + ia]);
        g_iao[o] = __float2half(sv[r * DFEAT + ia]);
        g_io [o] = __float2half(sv[r * DFEAT + iv]);
        g_aio[o] = __float2half(sa[r * DFEAT + iv]);
    }
}

// ---------------- persistent main kernel: 148 CTAs, 1024 units ----------------
// unit u: m = u>>9, rt = (u>>3)&63, cc = u&7 (column chunk of 8 tiles).
// Static contiguous ranges keep consecutive units on one X tile.
__global__ void __launch_bounds__(NTHREADS, 1)
supcon_main_kernel() {
    extern __shared__ char smem[];
    const uint32_t sb = smem_u32(smem);
    const int tid  = threadIdx.x;
    const int lane = tid & 31;
    const int wid  = tid >> 5;
    const int rg   = wid & 3;        // rows 32*rg .. 32*rg+31
    const int ch   = wid >> 2;       // 64-col half within the 128-wide tile
    const int ustart = (blockIdx.x * NUNITS) / NSM;
    const int uend   = ((blockIdx.x + 1) * NUNITS) / NSM;

    uint32_t dsto[4];
#pragma unroll
    for (int k = 0; k < 4; k++) {
        uint32_t u = (uint32_t)tid + k * 256u;
        dsto[k] = (u & ~7u) * 16u + (((u & 7u) ^ ((u >> 3) & 7u)) << 4);
    }

    uint32_t browoff[4], bxr[4];
    const int bn  = ((lane >> 4) << 3) + (lane & 7);
    const int bko = (lane >> 3) & 1;
#pragma unroll
    for (int nn = 0; nn < 4; nn++) {
        int nr = 16 * (4 * ch + nn) + bn;
        browoff[nn] = (uint32_t)nr * 128u;
        bxr[nn] = (uint32_t)(nr & 7);
    }

    uint32_t A[2][4][4];
    int last_xid = -1;

    for (int u = ustart; u < uend; u++) {
        const int m  = u >> 9;
        const int rt = (u >> 3) & 63;
        const int cc = u & 7;
        const __half* X = m ? g_aio : g_iao;
        const __half* Y = m ? g_io  : g_ao;
        const char* Yb = (const char*)Y + (size_t)cc * (8 * 16384);

        // prefetch Y tiles 0, 1 of this chunk
#pragma unroll
        for (int k = 0; k < 4; k++)
            cp16(sb + SB_Y0 + dsto[k], Yb + (size_t)(tid + k * 256) * 16);
        CP_COMMIT();
#pragma unroll
        for (int k = 0; k < 4; k++)
            cp16(sb + SB_Y1 + dsto[k], Yb + 16384 + (size_t)(tid + k * 256) * 16);
        CP_COMMIT();

        // (re)load X tile + A fragments when (m, rt) changes (rare: ranges are contiguous)
        if ((u >> 3) != last_xid) {
            last_xid = u >> 3;
            __syncthreads();
            const uint4* xg = (const uint4*)(X + (size_t)rt * TILE * DKEEP);
#pragma unroll
            for (int k = 0; k < 4; k++) {
                uint4 val = xg[tid + k * 256];
                *(uint4*)(smem + SB_X + dsto[k]) = val;
            }
            __syncthreads();
            int kc = lane >> 4;
#pragma unroll
            for (int rb = 0; rb < 2; rb++) {
                int row = 32 * rg + 16 * rb + (lane & 15);
#pragma unroll
                for (int kk = 0; kk < 4; kk++) {
                    uint32_t chunk = (uint32_t)(kk * 2 + kc);
                    uint32_t addr  = sb + SB_X + (uint32_t)row * 128u
                                   + ((chunk ^ (uint32_t)(row & 7)) << 4);
                    ldsm4(A[rb][kk], addr);
                }
            }
        }

        float accC[2][8][4], accP[2][8][4];
#pragma unroll
        for (int rb = 0; rb < 2; rb++)
#pragma unroll
            for (int f = 0; f < 8; f++)
#pragma unroll
                for (int c = 0; c < 4; c++) accP[rb][f][c] = -1e30f;
        float ps[8] = {0.f, 0.f, 0.f, 0.f, 0.f, 0.f, 0.f, 0.f};

        for (int j = 0; j < 8; j++) {
            if (j >= 6) { CP_WAIT(0); } else { CP_WAIT(1); }
            __syncthreads();
            const uint32_t sbY = sb + ((j & 1) ? SB_Y1 : SB_Y0);
            if (j & 1) do_tile(sbY, A, browoff, bxr, bko, accP, accC, ps);
            else       do_tile(sbY, A, browoff, bxr, bko, accC, accP, ps);
            __syncthreads();
            if (j + 2 < 8) {
                const char* src = Yb + (size_t)(j + 2) * 16384;
#pragma unroll
                for (int k = 0; k < 4; k++)
                    cp16(sbY + dsto[k], src + (size_t)(tid + k * 256) * 16);
                CP_COMMIT();
            }
        }

        // tail: last tile (j=7, odd) sits in accP
#pragma unroll
        for (int f = 0; f < 8; f++) {
            exp_frag(accP[0][f], ps[0], ps[1], ps[2], ps[3]);
            exp_frag(accP[1][f], ps[4], ps[5], ps[6], ps[7]);
        }

        // ---- flush partial row sums for this unit ----
        float rsA0 = ps[0] + ps[1];
        float rsA1 = ps[2] + ps[3];
        float rsB0 = ps[4] + ps[5];
        float rsB1 = ps[6] + ps[7];
#pragma unroll
        for (int o = 1; o < 4; o <<= 1) {
            rsA0 += __shfl_xor_sync(0xffffffffu, rsA0, o);
            rsA1 += __shfl_xor_sync(0xffffffffu, rsA1, o);
            rsB0 += __shfl_xor_sync(0xffffffffu, rsB0, o);
            rsB1 += __shfl_xor_sync(0xffffffffu, rsB1, o);
        }
        const int r0 = 32 * rg + (lane >> 2);
        float* rsum = (float*)(smem + (ch ? SB_RSUM1 : SB_RSUM0));
        if ((lane & 3) == 0) {
            rsum[r0]      = rsA0;
            rsum[r0 + 8]  = rsA1;
            rsum[r0 + 16] = rsB0;
            rsum[r0 + 24] = rsB1;
        }
        __syncthreads();
        if (tid < 128) {
            float tot = ((float*)(smem + SB_RSUM0))[tid] + ((float*)(smem + SB_RSUM1))[tid];
            atomicAdd(&g_rsum[m * B_ROWS + rt * TILE + tid], tot);
            if (cc == (rt >> 3)) {   // this chunk holds the diagonal block
                const uint4* xr = (const uint4*)(X + (size_t)(rt * TILE + tid) * DKEEP);
                const uint4* yr = (const uint4*)(Y + (size_t)(rt * TILE + tid) * DKEEP);
                float dg = 0.f;
#pragma unroll
                for (int i = 0; i < 8; i++) {
                    uint4 xv = xr[i];
                    uint4 yv = yr[i];
                    const uint32_t* xw = (const uint32_t*)&xv;
                    const uint32_t* yw = (const uint32_t*)&yv;
#pragma unroll
                    for (int w = 0; w < 4; w++) {
                        float2 xf = __half22float2(*(const __half2*)&xw[w]);
                        float2 yf = __half22float2(*(const __half2*)&yw[w]);
                        dg = fmaf(xf.x, yf.x, dg);
                        dg = fmaf(xf.y, yf.y, dg);
                    }
                }
                g_diag[m * B_ROWS + rt * TILE + tid] = dg;
            }
        }
        __syncthreads();
    }
}

// final: loss = mean over both matrices of (log(rsum) + SHIFT*ln2 - diag)
__global__ void reduce_kernel(float* __restrict__ out) {
    __shared__ float wred[8];
    const int tid = threadIdx.x;
    const int idx = blockIdx.x * 256 + tid;
    float tot = g_rsum[idx];
    float dg  = g_diag[idx];
    float lg;
    asm("lg2.approx.f32 %0, %1;" : "=f"(lg) : "f"(tot));
    float loss = (lg + SHIFTB) * LN2 - dg;
#pragma unroll
    for (int o = 1; o < 32; o <<= 1)
        loss += __shfl_xor_sync(0xffffffffu, loss, o);
    if ((tid & 31) == 0) wred[tid >> 5] = loss;
    __syncthreads();
    if (tid == 0) {
        float s = 0.f;
#pragma unroll
        for (int w = 0; w < 8; w++) s += wred[w];
        atomicAdd(out, s * (1.0f / (float)B_ROWS));
    }
}

// ---------------- launch ----------------
extern "C" void kernel_launch(void* const* d_in, const int* in_sizes, int n_in,
                              void* d_out, int out_size) {
    const float* a = (const float*)d_in[0];
    const float* v = (const float*)d_in[1];
    const int* ai = (const int*)d_in[2];
    const int* ii = (const int*)d_in[3];
    float* out = (float*)d_out;

    cudaFuncSetAttribute(supcon_main_kernel,
                         cudaFuncAttributeMaxDynamicSharedMemorySize, SMEM_BYTES);

    gather_kernel<<<B_ROWS / 32, 256>>>(a, v, ai, ii, out, out_size);
    supcon_main_kernel<<<NSM, NTHREADS, SMEM_BYTES>>>();
    reduce_kernel<<<2 * B_ROWS / 256, 256>>>(out);
}